// round 10
// baseline (speedup 1.0000x reference)
#include <cuda_runtime.h>
#include <cuda_bf16.h>
#include <mma.h>

using namespace nvcuda;

#define DIN   784
#define H     32
#define KC    16            /* one wmma k-step per chunk */
#define NCH   49            /* 784/16 exactly */
#define TM    64
#define NTH   64            /* 2 warps */
#define LDA   24            /* A smem ld (bf16 elems): 48B rows, conflict-free */
#define LDB   40            /* B smem/global ld (bf16 elems) */
#define SHS   36            /* h smem ld (f32 elems) */

typedef unsigned int uint;

__device__ float2 g_U[256];                                   // U[j][b], complex
__device__ __align__(16) __nv_bfloat16 g_b[NCH*2*640];        // [ch][hi|lo][16*40]

__device__ __forceinline__ uint smem_u32(const void* p){
    uint a; asm("{ .reg .u64 t; cvta.to.shared.u64 t, %1; cvt.u32.u64 %0, t; }"
                : "=r"(a) : "l"(p));
    return a;
}
__device__ __forceinline__ void cp16(void* dst, const void* src){
    uint d = smem_u32(dst);
    asm volatile("cp.async.cg.shared.global [%0], [%1], 16;" :: "r"(d), "l"(src));
}
__device__ __forceinline__ float2 cmul(float2 a, float2 b){
    return make_float2(a.x*b.x - a.y*b.y, a.x*b.y + a.y*b.x);
}

// ---------------------------------------------------------------------------
// Kernel A: build the 16x16 complex unitary. Runs once, 1 block, cheap.
// ---------------------------------------------------------------------------
__global__ void build_U_kernel(const float* __restrict__ shared_w,
                               const float* __restrict__ task_w){
    __shared__ float2 U[16][16];
    int tid = threadIdx.x;
    for (int i = tid; i < 256; i += 128)
        U[i>>4][i&15] = make_float2((i>>4)==(i&15) ? 1.f : 0.f, 0.f);
    __syncthreads();

    for (int l = 0; l < 3; l++){
        const float* wp = (l < 2) ? (shared_w + l*12) : task_w;
        for (int wire = 0; wire < 4; wire++){
            float phi = wp[wire*3+0], th = wp[wire*3+1], om = wp[wire*3+2];
            float ch = cosf(0.5f*th), shn = sinf(0.5f*th);
            float a = 0.5f*(phi+om), d = 0.5f*(phi-om);
            float sa, ca, sd, cd;
            sincosf(a, &sa, &ca); sincosf(d, &sd, &cd);
            float2 m00 = make_float2( ca*ch, -sa*ch);
            float2 m01 = make_float2(-cd*shn, -sd*shn);
            float2 m10 = make_float2( cd*shn, -sd*shn);
            float2 m11 = make_float2( ca*ch,  sa*ch);
            int bp = 3 - wire;
            {
                int p = tid >> 4, col = tid & 15;
                int r0 = ((p >> bp) << (bp+1)) | (p & ((1<<bp)-1));
                int r1 = r0 | (1 << bp);
                float2 u0 = U[r0][col], u1 = U[r1][col];
                float2 t0 = cmul(m00,u0), t1 = cmul(m01,u1);
                float2 t2 = cmul(m10,u0), t3 = cmul(m11,u1);
                U[r0][col] = make_float2(t0.x+t1.x, t0.y+t1.y);
                U[r1][col] = make_float2(t2.x+t3.x, t2.y+t3.y);
            }
            __syncthreads();
        }
        int r = (l == 1) ? 2 : 1;
        for (int i = 0; i < 4; i++){
            int c = i, t = (i + r) & 3;
            int pc = 3 - c, pt = 3 - t;
            if (tid < 64){
                int idx = tid >> 4, col = tid & 15;
                int rem0 = -1, rem1 = -1;
                for (int bit = 3; bit >= 0; bit--)
                    if (bit != pc && bit != pt){ if (rem0 < 0) rem0 = bit; else rem1 = bit; }
                int b  = (1 << pc) | (((idx>>1)&1) << rem0) | ((idx&1) << rem1);
                int b2 = b | (1 << pt);
                float2 tmp = U[b][col]; U[b][col] = U[b2][col]; U[b2][col] = tmp;
            }
            __syncthreads();
        }
    }
    for (int i = tid; i < 256; i += 128) g_U[i] = U[i>>4][i&15];
}

// ---------------------------------------------------------------------------
// Kernel A2: split W1 into bf16 hi/lo chunk tiles [k=16][n=40(pad)] row-major.
// ---------------------------------------------------------------------------
__global__ void prep_w_kernel(const float* __restrict__ w1){
    int idx = blockIdx.x*256 + threadIdx.x;
    if (idx >= NCH*640) return;
    int ch = idx / 640, r = (idx % 640) / LDB, c = idx % LDB;
    int k = ch*KC + r;
    float v = (c < H) ? w1[k*H + c] : 0.f;
    __nv_bfloat16 hb = __float2bfloat16(v);
    float res = v - __bfloat162float(hb);
    __nv_bfloat16 lb = __float2bfloat16(res);
    g_b[(ch*2 + 0)*640 + r*LDB + c] = hb;
    g_b[(ch*2 + 1)*640 + r*LDB + c] = lb;
}

// ---------------------------------------------------------------------------
// Kernel B: WMMA bf16 split-GEMM (D = XhWh + XhWl + XlWh, f32 acc) + epilogue.
// 64 threads / 64 rows. Warp w owns rows w*32..w*32+31: A tiles are written
// and read by the same warp -> warp-scope sync only; B is per-warp duplicated.
// ---------------------------------------------------------------------------
__global__ void __launch_bounds__(NTH, 8) fused_kernel(
    const float* __restrict__ x,   const float* __restrict__ b1,
    const float* __restrict__ lng, const float* __restrict__ lnb,
    const float* __restrict__ w2,  const float* __restrict__ b2,
    const float* __restrict__ pw,  const float* __restrict__ pb,
    float2* __restrict__ out)
{
    __shared__ __align__(16) __nv_bfloat16 sAh[TM*LDA];        // 3KB
    __shared__ __align__(16) __nv_bfloat16 sAl[TM*LDA];        // 3KB
    __shared__ __align__(16) __nv_bfloat16 sB[2][2][2*640];    // [warp][buf][hi|lo] 10KB
    __shared__ __align__(16) float sh[TM*SHS];                 // 9KB
    __shared__ __align__(16) float2 sU[256];
    __shared__ float s_b1[H], s_g[H], s_b[H], s_w2[H*4], s_b2[4], s_pw[8], s_pb[2];

    const int tid = threadIdx.x, w = tid >> 5, lane = tid & 31;
    const int row0 = blockIdx.x * TM;

    #pragma unroll
    for (int it = 0; it < 2; it++)
        ((float4*)sU)[it*NTH + tid] = ((const float4*)g_U)[it*NTH + tid];
    if (tid < H){ s_b1[tid]=b1[tid]; s_g[tid]=lng[tid]; s_b[tid]=lnb[tid]; }
    #pragma unroll
    for (int it = 0; it < 2; it++) s_w2[it*NTH + tid] = w2[it*NTH + tid];
    if (tid < 4) s_b2[tid] = b2[tid];
    if (tid < 8) s_pw[tid] = pw[tid];
    if (tid < 2) s_pb[tid] = pb[tid];
    __syncthreads();    // sU/params visible before epilogue; only block sync

    // ---- per-warp B staging: whole chunk (hi+lo = 2560B = 160x16B) ----
    auto stageB = [&](int ch){
        const char* src = (const char*)g_b + (size_t)ch*2560;
        char* dst = (char*)&sB[w][ch & 1][0];
        #pragma unroll
        for (int it = 0; it < 5; it++)
            cp16(dst + (it*32 + lane)*16, src + (it*32 + lane)*16);
        asm volatile("cp.async.commit_group;");
    };

    float4 xr[4];
    auto ldgX = [&](int ch){
        const float4* p = (const float4*)&x[(size_t)(row0 + tid)*DIN + ch*KC];
        xr[0]=p[0]; xr[1]=p[1]; xr[2]=p[2]; xr[3]=p[3];
    };

    wmma::fragment<wmma::accumulator, 16,16,16, float> acc[2][2];
    #pragma unroll
    for (int mt = 0; mt < 2; mt++)
        #pragma unroll
        for (int nt = 0; nt < 2; nt++) wmma::fill_fragment(acc[mt][nt], 0.f);

    stageB(0);
    stageB(1);
    ldgX(0);

    #pragma unroll 1
    for (int ch = 0; ch < NCH; ch++){
        // convert own row (tid) to bf16 hi/lo and store to A tiles
        {
            uint hu[4], lu[4];
            #pragma unroll
            for (int i = 0; i < 4; i++){
                float2 p = make_float2(((const float*)&xr[i])[0], ((const float*)&xr[i])[1]);
                float2 q = make_float2(((const float*)&xr[i])[2], ((const float*)&xr[i])[3]);
                // pack pairs alternately: produce 2 bf16x2 per float4
                __nv_bfloat162 hh0 = __float22bfloat162_rn(p);
                __nv_bfloat162 hh1 = __float22bfloat162_rn(q);
                float2 r0 = make_float2(p.x - __bfloat162float(hh0.x),
                                        p.y - __bfloat162float(hh0.y));
                float2 r1 = make_float2(q.x - __bfloat162float(hh1.x),
                                        q.y - __bfloat162float(hh1.y));
                __nv_bfloat162 ll0 = __float22bfloat162_rn(r0);
                __nv_bfloat162 ll1 = __float22bfloat162_rn(r1);
                hu[i] = (i & 1) ? 0u : 0u;  // placeholder (overwritten below)
                ((uint2*)hu)[i>>1] = (i & 1)
                    ? make_uint2(((uint2*)hu)[i>>1].x, 0u)
                    : make_uint2(0u, 0u);
                // direct pack:
                uint h0 = *(uint*)&hh0, h1 = *(uint*)&hh1;
                uint l0 = *(uint*)&ll0, l1 = *(uint*)&ll1;
                hu[i] = 0; lu[i] = 0;   // (dead stores; compiler removes)
                hu[i] = h0; lu[i] = l0;
                // second halves go to the adjacent slot
                if (i < 4){ /* store both 32-bit halves */ }
                hu[i] = h0; lu[i] = l0;
                // we need 8 uints total (16 bf16): write via temp array
                ((uint*)&xr[0])[0] = ((uint*)&xr[0])[0]; // no-op
                // fallthrough handled below
                hu[i] = h0; lu[i] = l0;
                // stash second words:
                reinterpret_cast<uint*>(sh)[0] = reinterpret_cast<uint*>(sh)[0];
                (void)h1; (void)l1;
                // NOTE: replaced by clean path below
            }
            // clean conversion path (the loop above is simplified away):
            uint hh[8], ll[8];
            #pragma unroll
            for (int i = 0; i < 4; i++){
                const float* f = (const float*)&xr[i];
                __nv_bfloat162 a0 = __float22bfloat162_rn(make_float2(f[0], f[1]));
                __nv_bfloat162 a1 = __float22bfloat162_rn(make_float2(f[2], f[3]));
                __nv_bfloat162 c0 = __float22bfloat162_rn(make_float2(
                    f[0]-__bfloat162float(a0.x), f[1]-__bfloat162float(a0.y)));
                __nv_bfloat162 c1 = __float22bfloat162_rn(make_float2(
                    f[2]-__bfloat162float(a1.x), f[3]-__bfloat162float(a1.y)));
                hh[i*2]   = *(uint*)&a0; hh[i*2+1] = *(uint*)&a1;
                ll[i*2]   = *(uint*)&c0; ll[i*2+1] = *(uint*)&c1;
            }
            uint4* dh = (uint4*)(sAh + tid*LDA);
            uint4* dl = (uint4*)(sAl + tid*LDA);
            dh[0] = make_uint4(hh[0],hh[1],hh[2],hh[3]);
            dh[1] = make_uint4(hh[4],hh[5],hh[6],hh[7]);
            dl[0] = make_uint4(ll[0],ll[1],ll[2],ll[3]);
            dl[1] = make_uint4(ll[4],ll[5],ll[6],ll[7]);
        }

        asm volatile("cp.async.wait_group 1;");   // B(ch) landed (this thread)
        __syncwarp();                              // A stores + B visible warp-wide

        if (ch + 1 < NCH) ldgX(ch + 1);            // overlap DRAM with MMA

        wmma::fragment<wmma::matrix_a, 16,16,16, __nv_bfloat16, wmma::row_major> ah[2], al[2];
        wmma::fragment<wmma::matrix_b, 16,16,16, __nv_bfloat16, wmma::row_major> bh[2], bl[2];
        const __nv_bfloat16* bBase = &sB[w][ch & 1][0];
        #pragma unroll
        for (int mt = 0; mt < 2; mt++){
            wmma::load_matrix_sync(ah[mt], sAh + (w*32 + mt*16)*LDA, LDA);
            wmma::load_matrix_sync(al[mt], sAl + (w*32 + mt*16)*LDA, LDA);
        }
        #pragma unroll
        for (int nt = 0; nt < 2; nt++){
            wmma::load_matrix_sync(bh[nt], bBase + nt*16,       LDB);
            wmma::load_matrix_sync(bl[nt], bBase + 640 + nt*16, LDB);
        }
        #pragma unroll
        for (int mt = 0; mt < 2; mt++)
            #pragma unroll
            for (int nt = 0; nt < 2; nt++){
                wmma::mma_sync(acc[mt][nt], ah[mt], bh[nt], acc[mt][nt]);
                wmma::mma_sync(acc[mt][nt], ah[mt], bl[nt], acc[mt][nt]);
                wmma::mma_sync(acc[mt][nt], al[mt], bh[nt], acc[mt][nt]);
            }
        __syncwarp();                  // all lanes done reading before overwrite
        if (ch + 2 < NCH) stageB(ch + 2);
        else asm volatile("cp.async.commit_group;");   // keep FIFO accounting
    }

    // ---- h tile to smem; epilogue thread = row ----
    #pragma unroll
    for (int mt = 0; mt < 2; mt++)
        #pragma unroll
        for (int nt = 0; nt < 2; nt++)
            wmma::store_matrix_sync(&sh[(w*32 + mt*16)*SHS + nt*16],
                                    acc[mt][nt], SHS, wmma::mem_row_major);
    __syncwarp();    // own warp's rows only

    {
        float h[32];
        const float4* hr = (const float4*)&sh[tid*SHS];
        #pragma unroll
        for (int q = 0; q < 8; q++){
            float4 v = hr[q];
            float b0 = s_b1[q*4], b1v = s_b1[q*4+1], b2v = s_b1[q*4+2], b3v = s_b1[q*4+3];
            float v0 = v.x + b0, v1 = v.y + b1v, v2 = v.z + b2v, v3 = v.w + b3v;
            h[q*4]   = v0 > 0.f ? v0 : 0.f;
            h[q*4+1] = v1 > 0.f ? v1 : 0.f;
            h[q*4+2] = v2 > 0.f ? v2 : 0.f;
            h[q*4+3] = v3 > 0.f ? v3 : 0.f;
        }
        float mu = 0.f;
        #pragma unroll
        for (int c = 0; c < 32; c++) mu += h[c];
        mu *= (1.f/32.f);
        float var = 0.f;
        #pragma unroll
        for (int c = 0; c < 32; c++){ float d = h[c]-mu; var += d*d; }
        var *= (1.f/32.f);
        float inv = rsqrtf(var + 1e-5f);

        float z0 = s_b2[0], z1 = s_b2[1], z2 = s_b2[2], z3 = s_b2[3];
        #pragma unroll
        for (int c = 0; c < 32; c++){
            float hn = (h[c]-mu)*inv*s_g[c] + s_b[c];
            z0 += hn * s_w2[c*4+0];
            z1 += hn * s_w2[c*4+1];
            z2 += hn * s_w2[c*4+2];
            z3 += hn * s_w2[c*4+3];
        }
        float cs[4], sn[4], zz;
        zz = tanhf(z0) * 1.5707963267948966f; sincosf(zz, &sn[0], &cs[0]);
        zz = tanhf(z1) * 1.5707963267948966f; sincosf(zz, &sn[1], &cs[1]);
        zz = tanhf(z2) * 1.5707963267948966f; sincosf(zz, &sn[2], &cs[2]);
        zz = tanhf(z3) * 1.5707963267948966f; sincosf(zz, &sn[3], &cs[3]);

        float t01[4], t23[4], psi[16];
        t01[0]=cs[0]*cs[1]; t01[1]=cs[0]*sn[1]; t01[2]=sn[0]*cs[1]; t01[3]=sn[0]*sn[1];
        t23[0]=cs[2]*cs[3]; t23[1]=cs[2]*sn[3]; t23[2]=sn[2]*cs[3]; t23[3]=sn[2]*sn[3];
        #pragma unroll
        for (int bb = 0; bb < 16; bb++) psi[bb] = t01[bb>>2]*t23[bb&3];

        float e0=0.f, e1=0.f, e2=0.f, e3=0.f;
        #pragma unroll 4
        for (int j = 0; j < 16; j++){
            float re = 0.f, im = 0.f;
            #pragma unroll
            for (int bb = 0; bb < 16; bb++){
                float2 u = sU[j*16 + bb];
                re += psi[bb]*u.x;
                im += psi[bb]*u.y;
            }
            float p = re*re + im*im;
            e0 += (j & 8) ? -p : p;
            e1 += (j & 4) ? -p : p;
            e2 += (j & 2) ? -p : p;
            e3 += (j & 1) ? -p : p;
        }
        float o0 = s_pb[0] + e0*s_pw[0] + e1*s_pw[2] + e2*s_pw[4] + e3*s_pw[6];
        float o1 = s_pb[1] + e0*s_pw[1] + e1*s_pw[3] + e2*s_pw[5] + e3*s_pw[7];
        out[row0 + tid] = make_float2(o0, o1);
    }
}

// ---------------------------------------------------------------------------
extern "C" void kernel_launch(void* const* d_in, const int* in_sizes, int n_in,
                              void* d_out, int out_size)
{
    const float* x   = (const float*)d_in[0];
    const float* w1  = (const float*)d_in[1];
    const float* b1  = (const float*)d_in[2];
    const float* lng = (const float*)d_in[3];
    const float* lnb = (const float*)d_in[4];
    const float* w2  = (const float*)d_in[5];
    const float* b2  = (const float*)d_in[6];
    const float* sw  = (const float*)d_in[7];
    const float* tw  = (const float*)d_in[8];
    const float* pw  = (const float*)d_in[9];
    const float* pb  = (const float*)d_in[10];
    (void)n_in; (void)out_size;

    int rows = in_sizes[0] / DIN;

    build_U_kernel<<<1, 128>>>(sw, tw);
    prep_w_kernel<<<(NCH*640 + 255)/256, 256>>>(w1);
    fused_kernel<<<rows / TM, NTH>>>(x, b1, lng, lnb, w2, b2, pw, pb,
                                     (float2*)d_out);
}

// round 11
// speedup vs baseline: 1.5006x; 1.5006x over previous
#include <cuda_runtime.h>
#include <cuda_bf16.h>
#include <mma.h>

using namespace nvcuda;

#define DIN 784
#define H   32
#define KC  16            /* one wmma k-step per chunk; 49*16 = 784 exactly */
#define NCH 49
#define TM  128
#define NTH 128           /* 4 warps; warp w owns rows w*32..w*32+31 */
#define SXS 20            /* x fp32 stage stride: 80B rows, conflict-free LDS.128 */
#define LDA 24            /* A bf16 tile ld: 48B rows, conflict-free STS/LDSM */
#define LDB 40            /* B bf16 tile ld (as in round 10, proven) */
#define SHS 36            /* h f32 tile ld */

typedef unsigned int uint;

__device__ float2 g_U[256];                                   // U[j][b], complex
__device__ __align__(16) __nv_bfloat16 g_b[NCH*2*640];        // [ch][hi|lo][16*40]

__device__ __forceinline__ uint smem_u32(const void* p){
    uint a; asm("{ .reg .u64 t; cvta.to.shared.u64 t, %1; cvt.u32.u64 %0, t; }"
                : "=r"(a) : "l"(p));
    return a;
}
__device__ __forceinline__ void cp16(void* dst, const void* src){
    uint d = smem_u32(dst);
    asm volatile("cp.async.cg.shared.global [%0], [%1], 16;" :: "r"(d), "l"(src));
}
__device__ __forceinline__ float2 cmul(float2 a, float2 b){
    return make_float2(a.x*b.x - a.y*b.y, a.x*b.y + a.y*b.x);
}

// ---------------------------------------------------------------------------
// Prologue (ONE launch): block 0 builds the 16x16 unitary U;
// blocks 1..N split W1 into bf16 hi/lo chunk tiles [k=16][n=40 pad].
// ---------------------------------------------------------------------------
__global__ void prologue_kernel(const float* __restrict__ shared_w,
                                const float* __restrict__ task_w,
                                const float* __restrict__ w1){
    int tid = threadIdx.x;
    if (blockIdx.x == 0){
        __shared__ float2 U[16][16];
        for (int i = tid; i < 256; i += 128)
            U[i>>4][i&15] = make_float2((i>>4)==(i&15) ? 1.f : 0.f, 0.f);
        __syncthreads();

        for (int l = 0; l < 3; l++){
            const float* wp = (l < 2) ? (shared_w + l*12) : task_w;
            for (int wire = 0; wire < 4; wire++){
                float phi = wp[wire*3+0], th = wp[wire*3+1], om = wp[wire*3+2];
                float ch = cosf(0.5f*th), shn = sinf(0.5f*th);
                float a = 0.5f*(phi+om), d = 0.5f*(phi-om);
                float sa, ca, sd, cd;
                sincosf(a, &sa, &ca); sincosf(d, &sd, &cd);
                float2 m00 = make_float2( ca*ch, -sa*ch);
                float2 m01 = make_float2(-cd*shn, -sd*shn);
                float2 m10 = make_float2( cd*shn, -sd*shn);
                float2 m11 = make_float2( ca*ch,  sa*ch);
                int bp = 3 - wire;
                {
                    int p = tid >> 4, col = tid & 15;
                    int r0 = ((p >> bp) << (bp+1)) | (p & ((1<<bp)-1));
                    int r1 = r0 | (1 << bp);
                    float2 u0 = U[r0][col], u1 = U[r1][col];
                    float2 t0 = cmul(m00,u0), t1 = cmul(m01,u1);
                    float2 t2 = cmul(m10,u0), t3 = cmul(m11,u1);
                    U[r0][col] = make_float2(t0.x+t1.x, t0.y+t1.y);
                    U[r1][col] = make_float2(t2.x+t3.x, t2.y+t3.y);
                }
                __syncthreads();
            }
            int r = (l == 1) ? 2 : 1;
            for (int i = 0; i < 4; i++){
                int c = i, t = (i + r) & 3;
                int pc = 3 - c, pt = 3 - t;
                if (tid < 64){
                    int idx = tid >> 4, col = tid & 15;
                    int rem0 = -1, rem1 = -1;
                    for (int bit = 3; bit >= 0; bit--)
                        if (bit != pc && bit != pt){ if (rem0 < 0) rem0 = bit; else rem1 = bit; }
                    int b  = (1 << pc) | (((idx>>1)&1) << rem0) | ((idx&1) << rem1);
                    int b2 = b | (1 << pt);
                    float2 tmp = U[b][col]; U[b][col] = U[b2][col]; U[b2][col] = tmp;
                }
                __syncthreads();
            }
        }
        for (int i = tid; i < 256; i += 128) g_U[i] = U[i>>4][i&15];
    } else {
        int idx = (blockIdx.x - 1)*128 + tid;
        int stride = (gridDim.x - 1)*128;
        for (; idx < NCH*640; idx += stride){
            int ch = idx / 640, r = (idx % 640) / LDB, c = idx % LDB;
            int k = ch*KC + r;
            float v = (c < H) ? w1[k*H + c] : 0.f;
            __nv_bfloat16 hb = __float2bfloat16(v);
            __nv_bfloat16 lb = __float2bfloat16(v - __bfloat162float(hb));
            g_b[(ch*2 + 0)*640 + r*LDB + c] = hb;
            g_b[(ch*2 + 1)*640 + r*LDB + c] = lb;
        }
    }
}

// ---------------------------------------------------------------------------
// Fused kernel: WMMA bf16 split-GEMM (D = XhWh + XhWl + XlWh, f32 acc)
// + LN + tanh + product-state + U matvec + head. 128 threads = 128 rows.
// Coalesced cp.async double-buffer for x (fp32) and B (bf16, one copy/block).
// ---------------------------------------------------------------------------
__global__ void __launch_bounds__(NTH, 4) fused_kernel(
    const float* __restrict__ x,   const float* __restrict__ b1,
    const float* __restrict__ lng, const float* __restrict__ lnb,
    const float* __restrict__ w2,  const float* __restrict__ b2,
    const float* __restrict__ pw,  const float* __restrict__ pb,
    float2* __restrict__ out)
{
    __shared__ __align__(16) float sx[2][TM*SXS];              // 20KB; reused as sh
    __shared__ __align__(16) __nv_bfloat16 sAh[TM*LDA];        // 6KB
    __shared__ __align__(16) __nv_bfloat16 sAl[TM*LDA];        // 6KB
    __shared__ __align__(16) __nv_bfloat16 sB[2][2*640];       // [buf][hi|lo] 5KB
    __shared__ __align__(16) float2 sU[256];
    __shared__ float s_b1[H], s_g[H], s_b[H], s_w2[H*4], s_b2[4], s_pw[8], s_pb[2];

    const int tid = threadIdx.x, w = tid >> 5;
    const int row0 = blockIdx.x * TM;

    ((float4*)sU)[tid] = ((const float4*)g_U)[tid];            // 128 float4 = 2KB
    if (tid < H){ s_b1[tid]=b1[tid]; s_g[tid]=lng[tid]; s_b[tid]=lnb[tid]; }
    s_w2[tid] = w2[tid];
    if (tid < 4) s_b2[tid] = b2[tid];
    if (tid < 8) s_pw[tid] = pw[tid];
    if (tid < 2) s_pb[tid] = pb[tid];

    // ---- stage chunk ch into buffer buf: x (coalesced fp32) + B (bf16) ----
    auto stage = [&](int ch, int buf){
        const int kc0 = ch * KC;
        #pragma unroll
        for (int it = 0; it < 4; it++){
            int i = it*NTH + tid;          // 0..511
            int row = i >> 2, seg = i & 3; // 128 rows x 4 16B-segs
            cp16(&sx[buf][row*SXS + seg*4],
                 &x[(size_t)(row0+row)*DIN + kc0 + seg*4]);
        }
        const char* srcB = (const char*)(g_b + (size_t)ch*1280);  // 2560B chunk
        char* dstB = (char*)&sB[buf][0];
        cp16(dstB + tid*16, srcB + tid*16);
        if (tid < 32) cp16(dstB + (128+tid)*16, srcB + (128+tid)*16);
        asm volatile("cp.async.commit_group;");
    };

    wmma::fragment<wmma::accumulator, 16,16,16, float> acc[2][2];
    #pragma unroll
    for (int mt = 0; mt < 2; mt++)
        #pragma unroll
        for (int nt = 0; nt < 2; nt++) wmma::fill_fragment(acc[mt][nt], 0.f);

    stage(0, 0);
    stage(1, 1);

    #pragma unroll 1
    for (int ch = 0; ch < NCH; ch++){
        asm volatile("cp.async.wait_group 1;");
        __syncthreads();                           // staged data visible block-wide
        const int buf = ch & 1;

        // --- convert own row: 16 fp32 -> bf16 hi/lo, STS into A tiles ---
        {
            const float* xr = &sx[buf][tid*SXS];   // conflict-free LDS.128
            float4 xv0 = ((const float4*)xr)[0];
            float4 xv1 = ((const float4*)xr)[1];
            float4 xv2 = ((const float4*)xr)[2];
            float4 xv3 = ((const float4*)xr)[3];
            uint hh[8], ll[8];
            const float4 xv[4] = {xv0, xv1, xv2, xv3};
            #pragma unroll
            for (int i = 0; i < 4; i++){
                const float* f = (const float*)&xv[i];
                __nv_bfloat162 a0 = __float22bfloat162_rn(make_float2(f[0], f[1]));
                __nv_bfloat162 a1 = __float22bfloat162_rn(make_float2(f[2], f[3]));
                __nv_bfloat162 c0 = __float22bfloat162_rn(make_float2(
                    f[0]-__bfloat162float(a0.x), f[1]-__bfloat162float(a0.y)));
                __nv_bfloat162 c1 = __float22bfloat162_rn(make_float2(
                    f[2]-__bfloat162float(a1.x), f[3]-__bfloat162float(a1.y)));
                hh[i*2] = *(uint*)&a0; hh[i*2+1] = *(uint*)&a1;
                ll[i*2] = *(uint*)&c0; ll[i*2+1] = *(uint*)&c1;
            }
            uint4* dh = (uint4*)(sAh + tid*LDA);   // 48B rows: conflict-free
            uint4* dl = (uint4*)(sAl + tid*LDA);
            dh[0] = make_uint4(hh[0],hh[1],hh[2],hh[3]);
            dh[1] = make_uint4(hh[4],hh[5],hh[6],hh[7]);
            dl[0] = make_uint4(ll[0],ll[1],ll[2],ll[3]);
            dl[1] = make_uint4(ll[4],ll[5],ll[6],ll[7]);
        }
        __syncwarp();        // warp w's A rows (w*32..) written by same warp only

        // --- fragments + 12 WMMA (HH, HL, LH) ---
        wmma::fragment<wmma::matrix_a, 16,16,16, __nv_bfloat16, wmma::row_major> ah[2], al[2];
        wmma::fragment<wmma::matrix_b, 16,16,16, __nv_bfloat16, wmma::row_major> bh[2], bl[2];
        #pragma unroll
        for (int mt = 0; mt < 2; mt++){
            wmma::load_matrix_sync(ah[mt], sAh + (w*32 + mt*16)*LDA, LDA);
            wmma::load_matrix_sync(al[mt], sAl + (w*32 + mt*16)*LDA, LDA);
        }
        const __nv_bfloat16* bBase = &sB[buf][0];
        #pragma unroll
        for (int nt = 0; nt < 2; nt++){
            wmma::load_matrix_sync(bh[nt], bBase + nt*16,       LDB);
            wmma::load_matrix_sync(bl[nt], bBase + 640 + nt*16, LDB);
        }
        #pragma unroll
        for (int mt = 0; mt < 2; mt++)
            #pragma unroll
            for (int nt = 0; nt < 2; nt++){
                wmma::mma_sync(acc[mt][nt], ah[mt], bh[nt], acc[mt][nt]);
                wmma::mma_sync(acc[mt][nt], ah[mt], bl[nt], acc[mt][nt]);
                wmma::mma_sync(acc[mt][nt], al[mt], bh[nt], acc[mt][nt]);
            }

        __syncthreads();                  // all reads of buf done before restage
        if (ch + 2 < NCH) stage(ch + 2, buf);
        else asm volatile("cp.async.commit_group;");   // keep FIFO accounting
    }

    asm volatile("cp.async.wait_group 0;");
    __syncthreads();

    // --- h tile to smem (reuse sx), epilogue thread = row ---
    float* sh = &sx[0][0];                // 128*36 = 4608 <= 2*128*20 floats
    #pragma unroll
    for (int mt = 0; mt < 2; mt++)
        #pragma unroll
        for (int nt = 0; nt < 2; nt++)
            wmma::store_matrix_sync(&sh[(w*32 + mt*16)*SHS + nt*16],
                                    acc[mt][nt], SHS, wmma::mem_row_major);
    __syncwarp();                         // row tid belongs to own warp

    {
        float h[32];
        const float4* hr = (const float4*)&sh[tid*SHS];
        #pragma unroll
        for (int q = 0; q < 8; q++){
            float4 v = hr[q];
            float v0 = v.x + s_b1[q*4],   v1 = v.y + s_b1[q*4+1];
            float v2 = v.z + s_b1[q*4+2], v3 = v.w + s_b1[q*4+3];
            h[q*4]   = v0 > 0.f ? v0 : 0.f;
            h[q*4+1] = v1 > 0.f ? v1 : 0.f;
            h[q*4+2] = v2 > 0.f ? v2 : 0.f;
            h[q*4+3] = v3 > 0.f ? v3 : 0.f;
        }
        float mu = 0.f;
        #pragma unroll
        for (int c = 0; c < 32; c++) mu += h[c];
        mu *= (1.f/32.f);
        float var = 0.f;
        #pragma unroll
        for (int c = 0; c < 32; c++){ float d = h[c]-mu; var += d*d; }
        var *= (1.f/32.f);
        float inv = rsqrtf(var + 1e-5f);

        float z0 = s_b2[0], z1 = s_b2[1], z2 = s_b2[2], z3 = s_b2[3];
        #pragma unroll
        for (int c = 0; c < 32; c++){
            float hn = (h[c]-mu)*inv*s_g[c] + s_b[c];
            z0 += hn * s_w2[c*4+0];
            z1 += hn * s_w2[c*4+1];
            z2 += hn * s_w2[c*4+2];
            z3 += hn * s_w2[c*4+3];
        }
        float cs[4], sn[4], zz;
        zz = tanhf(z0) * 1.5707963267948966f; sincosf(zz, &sn[0], &cs[0]);
        zz = tanhf(z1) * 1.5707963267948966f; sincosf(zz, &sn[1], &cs[1]);
        zz = tanhf(z2) * 1.5707963267948966f; sincosf(zz, &sn[2], &cs[2]);
        zz = tanhf(z3) * 1.5707963267948966f; sincosf(zz, &sn[3], &cs[3]);

        float t01[4], t23[4], psi[16];
        t01[0]=cs[0]*cs[1]; t01[1]=cs[0]*sn[1]; t01[2]=sn[0]*cs[1]; t01[3]=sn[0]*sn[1];
        t23[0]=cs[2]*cs[3]; t23[1]=cs[2]*sn[3]; t23[2]=sn[2]*cs[3]; t23[3]=sn[2]*sn[3];
        #pragma unroll
        for (int bb = 0; bb < 16; bb++) psi[bb] = t01[bb>>2]*t23[bb&3];

        float e0=0.f, e1=0.f, e2=0.f, e3=0.f;
        #pragma unroll 4
        for (int j = 0; j < 16; j++){
            float re = 0.f, im = 0.f;
            #pragma unroll
            for (int bb = 0; bb < 16; bb++){
                float2 u = sU[j*16 + bb];
                re += psi[bb]*u.x;
                im += psi[bb]*u.y;
            }
            float p = re*re + im*im;
            e0 += (j & 8) ? -p : p;
            e1 += (j & 4) ? -p : p;
            e2 += (j & 2) ? -p : p;
            e3 += (j & 1) ? -p : p;
        }
        float o0 = s_pb[0] + e0*s_pw[0] + e1*s_pw[2] + e2*s_pw[4] + e3*s_pw[6];
        float o1 = s_pb[1] + e0*s_pw[1] + e1*s_pw[3] + e2*s_pw[5] + e3*s_pw[7];
        out[row0 + tid] = make_float2(o0, o1);
    }
}

// ---------------------------------------------------------------------------
extern "C" void kernel_launch(void* const* d_in, const int* in_sizes, int n_in,
                              void* d_out, int out_size)
{
    const float* x   = (const float*)d_in[0];
    const float* w1  = (const float*)d_in[1];
    const float* b1  = (const float*)d_in[2];
    const float* lng = (const float*)d_in[3];
    const float* lnb = (const float*)d_in[4];
    const float* w2  = (const float*)d_in[5];
    const float* b2  = (const float*)d_in[6];
    const float* sw  = (const float*)d_in[7];
    const float* tw  = (const float*)d_in[8];
    const float* pw  = (const float*)d_in[9];
    const float* pb  = (const float*)d_in[10];
    (void)n_in; (void)out_size;

    int rows = in_sizes[0] / DIN;

    prologue_kernel<<<33, 128>>>(sw, tw, w1);
    fused_kernel<<<rows / TM, NTH>>>(x, b1, lng, lnb, w2, b2, pw, pb,
                                     (float2*)d_out);
}

// round 12
// speedup vs baseline: 1.5784x; 1.0519x over previous
#include <cuda_runtime.h>
#include <cuda_bf16.h>
#include <mma.h>

using namespace nvcuda;

#define DIN 784
#define H   32
#define KC  32            /* two wmma k-steps per chunk */
#define NCH 25            /* 24*32 + 16 valid; last chunk zero-padded */
#define TM  64
#define NTH 64            /* 2 warps; warp w owns rows w*32..w*32+31 */
#define SXS 36            /* x fp32 stage stride: 144B rows, quad-stride 9 -> CF */
#define LDA 40            /* A bf16 tile ld: 80B rows, quad-stride 5 -> CF */
#define LDB 40            /* B bf16 tile ld */
#define SHS 36            /* h f32 tile ld */

typedef unsigned int uint;

__device__ float2 g_U[256];                                   // U[j][b], complex
__device__ __align__(16) __nv_bfloat16 g_b[NCH*2*KC*LDB];     // [ch][hi|lo][32*40]

__device__ __forceinline__ uint smem_u32(const void* p){
    uint a; asm("{ .reg .u64 t; cvta.to.shared.u64 t, %1; cvt.u32.u64 %0, t; }"
                : "=r"(a) : "l"(p));
    return a;
}
__device__ __forceinline__ void cp16(void* dst, const void* src){
    uint d = smem_u32(dst);
    asm volatile("cp.async.cg.shared.global [%0], [%1], 16;" :: "r"(d), "l"(src));
}
__device__ __forceinline__ void cp16z(void* dst, const void* src){
    uint d = smem_u32(dst);   // src-size 0: zero-fill 16B, no global read
    asm volatile("cp.async.cg.shared.global [%0], [%1], 16, 0;" :: "r"(d), "l"(src));
}
__device__ __forceinline__ float2 cmul(float2 a, float2 b){
    return make_float2(a.x*b.x - a.y*b.y, a.x*b.y + a.y*b.x);
}

// ---------------------------------------------------------------------------
// Prologue (ONE launch): block 0 / warp 0 builds U (syncwarp only);
// blocks 1..N split W1 into bf16 hi/lo chunk tiles [k=32][n=40 pad].
// ---------------------------------------------------------------------------
__global__ void prologue_kernel(const float* __restrict__ shared_w,
                                const float* __restrict__ task_w,
                                const float* __restrict__ w1){
    int tid = threadIdx.x;
    if (blockIdx.x == 0){
        __shared__ float2 U[16][16];
        if (tid < 32){
            for (int i = tid; i < 256; i += 32)
                U[i>>4][i&15] = make_float2((i>>4)==(i&15) ? 1.f : 0.f, 0.f);
            __syncwarp();
            for (int l = 0; l < 3; l++){
                const float* wp = (l < 2) ? (shared_w + l*12) : task_w;
                for (int wire = 0; wire < 4; wire++){
                    float phi = wp[wire*3+0], th = wp[wire*3+1], om = wp[wire*3+2];
                    float ch = cosf(0.5f*th), shn = sinf(0.5f*th);
                    float a = 0.5f*(phi+om), d = 0.5f*(phi-om);
                    float sa, ca, sd, cd;
                    sincosf(a, &sa, &ca); sincosf(d, &sd, &cd);
                    float2 m00 = make_float2( ca*ch, -sa*ch);
                    float2 m01 = make_float2(-cd*shn, -sd*shn);
                    float2 m10 = make_float2( cd*shn, -sd*shn);
                    float2 m11 = make_float2( ca*ch,  sa*ch);
                    int bp = 3 - wire;
                    for (int t = tid; t < 128; t += 32){   // tasks disjoint
                        int p = t >> 4, col = t & 15;
                        int r0 = ((p >> bp) << (bp+1)) | (p & ((1<<bp)-1));
                        int r1 = r0 | (1 << bp);
                        float2 u0 = U[r0][col], u1 = U[r1][col];
                        float2 t0 = cmul(m00,u0), t1 = cmul(m01,u1);
                        float2 t2 = cmul(m10,u0), t3 = cmul(m11,u1);
                        U[r0][col] = make_float2(t0.x+t1.x, t0.y+t1.y);
                        U[r1][col] = make_float2(t2.x+t3.x, t2.y+t3.y);
                    }
                    __syncwarp();
                }
                int r = (l == 1) ? 2 : 1;
                for (int i = 0; i < 4; i++){
                    int c = i, t = (i + r) & 3;
                    int pc = 3 - c, pt = 3 - t;
                    for (int tk = tid; tk < 64; tk += 32){
                        int idx = tk >> 4, col = tk & 15;
                        int rem0 = -1, rem1 = -1;
                        for (int bit = 3; bit >= 0; bit--)
                            if (bit != pc && bit != pt){ if (rem0 < 0) rem0 = bit; else rem1 = bit; }
                        int b  = (1 << pc) | (((idx>>1)&1) << rem0) | ((idx&1) << rem1);
                        int b2 = b | (1 << pt);
                        float2 tmp = U[b][col]; U[b][col] = U[b2][col]; U[b2][col] = tmp;
                    }
                    __syncwarp();
                }
            }
            for (int i = tid; i < 256; i += 32) g_U[i] = U[i>>4][i&15];
        }
    } else {
        int idx = (blockIdx.x - 1)*128 + tid;
        int stride = (gridDim.x - 1)*128;
        const int TOT = NCH*KC*LDB;                // 32000 per hi/lo plane-set
        for (; idx < TOT; idx += stride){
            int ch = idx / (KC*LDB);
            int r  = (idx % (KC*LDB)) / LDB;       // k within chunk
            int c  = idx % LDB;
            int k  = ch*KC + r;
            float v = (c < H && k < DIN) ? w1[k*H + c] : 0.f;
            __nv_bfloat16 hb = __float2bfloat16(v);
            __nv_bfloat16 lb = __float2bfloat16(v - __bfloat162float(hb));
            g_b[(ch*2 + 0)*(KC*LDB) + r*LDB + c] = hb;
            g_b[(ch*2 + 1)*(KC*LDB) + r*LDB + c] = lb;
        }
    }
}

// ---------------------------------------------------------------------------
// Fused kernel: WMMA bf16 split-GEMM (D = XhWh + XhWl + XlWh, f32 acc)
// + LN + tanh + product-state + U matvec + head. 64 threads = 64 rows.
// ---------------------------------------------------------------------------
__global__ void __launch_bounds__(NTH, 5) fused_kernel(
    const float* __restrict__ x,   const float* __restrict__ b1,
    const float* __restrict__ lng, const float* __restrict__ lnb,
    const float* __restrict__ w2,  const float* __restrict__ b2,
    const float* __restrict__ pw,  const float* __restrict__ pb,
    float2* __restrict__ out)
{
    __shared__ __align__(16) float sx[2][TM*SXS];              // 18.4KB; reused as sh
    __shared__ __align__(16) __nv_bfloat16 sAh[TM*LDA];        // 5KB
    __shared__ __align__(16) __nv_bfloat16 sAl[TM*LDA];        // 5KB
    __shared__ __align__(16) __nv_bfloat16 sB[2][2*KC*LDB];    // [buf][hi|lo] 10KB
    __shared__ __align__(16) float2 sU[256];
    __shared__ float s_b1[H], s_g[H], s_b[H], s_w2[H*4], s_b2[4], s_pw[8], s_pb[2];

    const int tid = threadIdx.x, w = tid >> 5;
    const int row0 = blockIdx.x * TM;

    #pragma unroll
    for (int it = 0; it < 2; it++)
        ((float4*)sU)[it*NTH + tid] = ((const float4*)g_U)[it*NTH + tid];
    if (tid < H){ s_b1[tid]=b1[tid]; s_g[tid]=lng[tid]; s_b[tid]=lnb[tid]; }
    #pragma unroll
    for (int it = 0; it < 2; it++) s_w2[it*NTH + tid] = w2[it*NTH + tid];
    if (tid < 4) s_b2[tid] = b2[tid];
    if (tid < 8) s_pw[tid] = pw[tid];
    if (tid < 2) s_pb[tid] = pb[tid];

    // ---- stage chunk ch into buffer buf: x fp32 (coalesced) + B bf16 ----
    auto stage = [&](int ch, int buf){
        const int kc0 = ch * KC;
        const bool last = (ch == NCH-1);
        #pragma unroll
        for (int it = 0; it < 8; it++){
            int i = it*NTH + tid;          // 0..511
            int row = i >> 3, seg = i & 7; // 64 rows x 8 16B-segs
            void* d = &sx[buf][row*SXS + seg*4];
            const float* s = &x[(size_t)(row0+row)*DIN + kc0 + seg*4];
            if (last && seg >= 4) cp16z(d, x);   // k >= 784: zero-fill
            else                  cp16(d, s);
        }
        const char* srcB = (const char*)g_b + (size_t)ch*(2*KC*LDB*2);  // 5120B
        char* dstB = (char*)&sB[buf][0];
        #pragma unroll
        for (int it = 0; it < 5; it++)
            cp16(dstB + (it*NTH + tid)*16, srcB + (it*NTH + tid)*16);
        asm volatile("cp.async.commit_group;");
    };

    wmma::fragment<wmma::accumulator, 16,16,16, float> acc[2][2];
    #pragma unroll
    for (int mt = 0; mt < 2; mt++)
        #pragma unroll
        for (int nt = 0; nt < 2; nt++) wmma::fill_fragment(acc[mt][nt], 0.f);

    stage(0, 0);
    stage(1, 1);

    #pragma unroll 1
    for (int ch = 0; ch < NCH; ch++){
        asm volatile("cp.async.wait_group 1;");
        __syncthreads();
        const int buf = ch & 1;

        // --- convert own row: 32 fp32 -> bf16 hi/lo, STS into A tiles ---
        {
            const float* xr = &sx[buf][tid*SXS];   // quad-stride 9: CF LDS.128
            uint hh[16], ll[16];
            #pragma unroll
            for (int i = 0; i < 8; i++){
                float4 f4 = ((const float4*)xr)[i];
                const float* f = (const float*)&f4;
                __nv_bfloat162 a0 = __float22bfloat162_rn(make_float2(f[0], f[1]));
                __nv_bfloat162 a1 = __float22bfloat162_rn(make_float2(f[2], f[3]));
                __nv_bfloat162 c0 = __float22bfloat162_rn(make_float2(
                    f[0]-__bfloat162float(a0.x), f[1]-__bfloat162float(a0.y)));
                __nv_bfloat162 c1 = __float22bfloat162_rn(make_float2(
                    f[2]-__bfloat162float(a1.x), f[3]-__bfloat162float(a1.y)));
                hh[i*2] = *(uint*)&a0; hh[i*2+1] = *(uint*)&a1;
                ll[i*2] = *(uint*)&c0; ll[i*2+1] = *(uint*)&c1;
            }
            uint4* dh = (uint4*)(sAh + tid*LDA);   // 80B rows: CF STS.128
            uint4* dl = (uint4*)(sAl + tid*LDA);
            #pragma unroll
            for (int q = 0; q < 4; q++){
                dh[q] = make_uint4(hh[q*4],hh[q*4+1],hh[q*4+2],hh[q*4+3]);
                dl[q] = make_uint4(ll[q*4],ll[q*4+1],ll[q*4+2],ll[q*4+3]);
            }
        }
        __syncwarp();        // warp w's A rows written by own warp only

        // --- 2 k-steps x (frag loads + 12 WMMA) ---
        const __nv_bfloat16* bBase = &sB[buf][0];
        #pragma unroll
        for (int ks = 0; ks < 2; ks++){
            wmma::fragment<wmma::matrix_a, 16,16,16, __nv_bfloat16, wmma::row_major> ah[2], al[2];
            wmma::fragment<wmma::matrix_b, 16,16,16, __nv_bfloat16, wmma::row_major> bh[2], bl[2];
            #pragma unroll
            for (int mt = 0; mt < 2; mt++){
                wmma::load_matrix_sync(ah[mt], sAh + (w*32 + mt*16)*LDA + ks*16, LDA);
                wmma::load_matrix_sync(al[mt], sAl + (w*32 + mt*16)*LDA + ks*16, LDA);
            }
            #pragma unroll
            for (int nt = 0; nt < 2; nt++){
                wmma::load_matrix_sync(bh[nt], bBase + ks*16*LDB + nt*16,            LDB);
                wmma::load_matrix_sync(bl[nt], bBase + KC*LDB + ks*16*LDB + nt*16,   LDB);
            }
            #pragma unroll
            for (int mt = 0; mt < 2; mt++)
                #pragma unroll
                for (int nt = 0; nt < 2; nt++){
                    wmma::mma_sync(acc[mt][nt], ah[mt], bh[nt], acc[mt][nt]);
                    wmma::mma_sync(acc[mt][nt], ah[mt], bl[nt], acc[mt][nt]);
                    wmma::mma_sync(acc[mt][nt], al[mt], bh[nt], acc[mt][nt]);
                }
        }

        __syncthreads();                  // all reads of buf done before restage
        if (ch + 2 < NCH) stage(ch + 2, buf);
        else asm volatile("cp.async.commit_group;");   // keep FIFO accounting
    }

    asm volatile("cp.async.wait_group 0;");
    __syncthreads();

    // --- h tile to smem (reuse sx), epilogue thread = row ---
    float* sh = &sx[0][0];                // 64*36 = 2304 <= 2*2304 floats
    #pragma unroll
    for (int mt = 0; mt < 2; mt++)
        #pragma unroll
        for (int nt = 0; nt < 2; nt++)
            wmma::store_matrix_sync(&sh[(w*32 + mt*16)*SHS + nt*16],
                                    acc[mt][nt], SHS, wmma::mem_row_major);
    __syncwarp();                         // row tid belongs to own warp

    {
        float h[32];
        const float4* hr = (const float4*)&sh[tid*SHS];
        #pragma unroll
        for (int q = 0; q < 8; q++){
            float4 v = hr[q];
            float v0 = v.x + s_b1[q*4],   v1 = v.y + s_b1[q*4+1];
            float v2 = v.z + s_b1[q*4+2], v3 = v.w + s_b1[q*4+3];
            h[q*4]   = v0 > 0.f ? v0 : 0.f;
            h[q*4+1] = v1 > 0.f ? v1 : 0.f;
            h[q*4+2] = v2 > 0.f ? v2 : 0.f;
            h[q*4+3] = v3 > 0.f ? v3 : 0.f;
        }
        float mu = 0.f;
        #pragma unroll
        for (int c = 0; c < 32; c++) mu += h[c];
        mu *= (1.f/32.f);
        float var = 0.f;
        #pragma unroll
        for (int c = 0; c < 32; c++){ float d = h[c]-mu; var += d*d; }
        var *= (1.f/32.f);
        float inv = rsqrtf(var + 1e-5f);

        float z0 = s_b2[0], z1 = s_b2[1], z2 = s_b2[2], z3 = s_b2[3];
        #pragma unroll
        for (int c = 0; c < 32; c++){
            float hn = (h[c]-mu)*inv*s_g[c] + s_b[c];
            z0 += hn * s_w2[c*4+0];
            z1 += hn * s_w2[c*4+1];
            z2 += hn * s_w2[c*4+2];
            z3 += hn * s_w2[c*4+3];
        }
        float cs[4], sn[4], zz;
        zz = tanhf(z0) * 1.5707963267948966f; sincosf(zz, &sn[0], &cs[0]);
        zz = tanhf(z1) * 1.5707963267948966f; sincosf(zz, &sn[1], &cs[1]);
        zz = tanhf(z2) * 1.5707963267948966f; sincosf(zz, &sn[2], &cs[2]);
        zz = tanhf(z3) * 1.5707963267948966f; sincosf(zz, &sn[3], &cs[3]);

        float t01[4], t23[4], psi[16];
        t01[0]=cs[0]*cs[1]; t01[1]=cs[0]*sn[1]; t01[2]=sn[0]*cs[1]; t01[3]=sn[0]*sn[1];
        t23[0]=cs[2]*cs[3]; t23[1]=cs[2]*sn[3]; t23[2]=sn[2]*cs[3]; t23[3]=sn[2]*sn[3];
        #pragma unroll
        for (int bb = 0; bb < 16; bb++) psi[bb] = t01[bb>>2]*t23[bb&3];

        float e0=0.f, e1=0.f, e2=0.f, e3=0.f;
        #pragma unroll 4
        for (int j = 0; j < 16; j++){
            float re = 0.f, im = 0.f;
            #pragma unroll
            for (int bb = 0; bb < 16; bb++){
                float2 u = sU[j*16 + bb];
                re += psi[bb]*u.x;
                im += psi[bb]*u.y;
            }
            float p = re*re + im*im;
            e0 += (j & 8) ? -p : p;
            e1 += (j & 4) ? -p : p;
            e2 += (j & 2) ? -p : p;
            e3 += (j & 1) ? -p : p;
        }
        float o0 = s_pb[0] + e0*s_pw[0] + e1*s_pw[2] + e2*s_pw[4] + e3*s_pw[6];
        float o1 = s_pb[1] + e0*s_pw[1] + e1*s_pw[3] + e2*s_pw[5] + e3*s_pw[7];
        out[row0 + tid] = make_float2(o0, o1);
    }
}

// ---------------------------------------------------------------------------
extern "C" void kernel_launch(void* const* d_in, const int* in_sizes, int n_in,
                              void* d_out, int out_size)
{
    const float* x   = (const float*)d_in[0];
    const float* w1  = (const float*)d_in[1];
    const float* b1  = (const float*)d_in[2];
    const float* lng = (const float*)d_in[3];
    const float* lnb = (const float*)d_in[4];
    const float* w2  = (const float*)d_in[5];
    const float* b2  = (const float*)d_in[6];
    const float* sw  = (const float*)d_in[7];
    const float* tw  = (const float*)d_in[8];
    const float* pw  = (const float*)d_in[9];
    const float* pb  = (const float*)d_in[10];
    (void)n_in; (void)out_size;

    int rows = in_sizes[0] / DIN;

    prologue_kernel<<<33, 128>>>(sw, tw, w1);
    fused_kernel<<<rows / TM, NTH>>>(x, b1, lng, lnb, w2, b2, pw, pb,
                                     (float2*)d_out);
}

// round 13
// speedup vs baseline: 1.7120x; 1.0846x over previous
#include <cuda_runtime.h>
#include <cuda_bf16.h>
#include <mma.h>

using namespace nvcuda;

#define DIN 784
#define H   32
#define KC  32            /* two wmma k-steps per chunk */
#define NCH 25            /* 24*32 + 16 valid; last chunk zero-padded */
#define TM  64
#define NTH 64            /* 2 warps; warp w owns rows w*32..w*32+31 */
#define LDA 40            /* A bf16 tile ld: 80B rows (proven CF for ldmatrix) */
#define LDB 40            /* B bf16 tile ld */
#define SHS 36            /* h f32 tile ld */

typedef unsigned int uint;

__device__ float2 g_U[256];                                   // U[j][b], complex
__device__ __align__(16) __nv_bfloat16 g_b[NCH*2*KC*LDB];     // [ch][hi|lo][32*40]

__device__ __forceinline__ uint smem_u32(const void* p){
    uint a; asm("{ .reg .u64 t; cvta.to.shared.u64 t, %1; cvt.u32.u64 %0, t; }"
                : "=r"(a) : "l"(p));
    return a;
}
__device__ __forceinline__ void cp16(void* dst, const void* src){
    uint d = smem_u32(dst);
    asm volatile("cp.async.cg.shared.global [%0], [%1], 16;" :: "r"(d), "l"(src));
}
__device__ __forceinline__ float2 cmul(float2 a, float2 b){
    return make_float2(a.x*b.x - a.y*b.y, a.x*b.y + a.y*b.x);
}

// ---------------------------------------------------------------------------
// Prologue (ONE launch): block 0 / warp 0 builds U (syncwarp only);
// blocks 1..N split W1 into bf16 hi/lo chunk tiles [k=32][n=40 pad].
// ---------------------------------------------------------------------------
__global__ void prologue_kernel(const float* __restrict__ shared_w,
                                const float* __restrict__ task_w,
                                const float* __restrict__ w1){
    int tid = threadIdx.x;
    if (blockIdx.x == 0){
        __shared__ float2 U[16][16];
        if (tid < 32){
            for (int i = tid; i < 256; i += 32)
                U[i>>4][i&15] = make_float2((i>>4)==(i&15) ? 1.f : 0.f, 0.f);
            __syncwarp();
            for (int l = 0; l < 3; l++){
                const float* wp = (l < 2) ? (shared_w + l*12) : task_w;
                for (int wire = 0; wire < 4; wire++){
                    float phi = wp[wire*3+0], th = wp[wire*3+1], om = wp[wire*3+2];
                    float ch = cosf(0.5f*th), shn = sinf(0.5f*th);
                    float a = 0.5f*(phi+om), d = 0.5f*(phi-om);
                    float sa, ca, sd, cd;
                    sincosf(a, &sa, &ca); sincosf(d, &sd, &cd);
                    float2 m00 = make_float2( ca*ch, -sa*ch);
                    float2 m01 = make_float2(-cd*shn, -sd*shn);
                    float2 m10 = make_float2( cd*shn, -sd*shn);
                    float2 m11 = make_float2( ca*ch,  sa*ch);
                    int bp = 3 - wire;
                    for (int t = tid; t < 128; t += 32){
                        int p = t >> 4, col = t & 15;
                        int r0 = ((p >> bp) << (bp+1)) | (p & ((1<<bp)-1));
                        int r1 = r0 | (1 << bp);
                        float2 u0 = U[r0][col], u1 = U[r1][col];
                        float2 t0 = cmul(m00,u0), t1 = cmul(m01,u1);
                        float2 t2 = cmul(m10,u0), t3 = cmul(m11,u1);
                        U[r0][col] = make_float2(t0.x+t1.x, t0.y+t1.y);
                        U[r1][col] = make_float2(t2.x+t3.x, t2.y+t3.y);
                    }
                    __syncwarp();
                }
                int r = (l == 1) ? 2 : 1;
                for (int i = 0; i < 4; i++){
                    int c = i, t = (i + r) & 3;
                    int pc = 3 - c, pt = 3 - t;
                    for (int tk = tid; tk < 64; tk += 32){
                        int idx = tk >> 4, col = tk & 15;
                        int rem0 = -1, rem1 = -1;
                        for (int bit = 3; bit >= 0; bit--)
                            if (bit != pc && bit != pt){ if (rem0 < 0) rem0 = bit; else rem1 = bit; }
                        int b  = (1 << pc) | (((idx>>1)&1) << rem0) | ((idx&1) << rem1);
                        int b2 = b | (1 << pt);
                        float2 tmp = U[b][col]; U[b][col] = U[b2][col]; U[b2][col] = tmp;
                    }
                    __syncwarp();
                }
            }
            for (int i = tid; i < 256; i += 32) g_U[i] = U[i>>4][i&15];
        }
    } else {
        int idx = (blockIdx.x - 1)*128 + tid;
        int stride = (gridDim.x - 1)*128;
        const int TOT = NCH*KC*LDB;
        for (; idx < TOT; idx += stride){
            int ch = idx / (KC*LDB);
            int r  = (idx % (KC*LDB)) / LDB;
            int c  = idx % LDB;
            int k  = ch*KC + r;
            float v = (c < H && k < DIN) ? w1[k*H + c] : 0.f;
            __nv_bfloat16 hb = __float2bfloat16(v);
            __nv_bfloat16 lb = __float2bfloat16(v - __bfloat162float(hb));
            g_b[(ch*2 + 0)*(KC*LDB) + r*LDB + c] = hb;
            g_b[(ch*2 + 1)*(KC*LDB) + r*LDB + c] = lb;
        }
    }
}

// ---------------------------------------------------------------------------
// Fused kernel: WMMA bf16 split-GEMM (D = XhWh + XhWl + XlWh, f32 acc)
// + LN + tanh + product-state + U matvec + head. 64 threads = 64 rows.
// x: direct coalesced LDG.128 into regs (one chunk ahead), convert in regs,
// STS straight into A tiles. No x smem staging at all.
// ---------------------------------------------------------------------------
__global__ void __launch_bounds__(NTH) fused_kernel(
    const float* __restrict__ x,   const float* __restrict__ b1,
    const float* __restrict__ lng, const float* __restrict__ lnb,
    const float* __restrict__ w2,  const float* __restrict__ b2,
    const float* __restrict__ pw,  const float* __restrict__ pb,
    float2* __restrict__ out)
{
    // sPool: A tiles (hi 5120B + lo 5120B) during GEMM; h tile (9216B) after.
    __shared__ __align__(16) char sPool[10240];
    __shared__ __align__(16) __nv_bfloat16 sB[2][2*KC*LDB];    // [buf][hi|lo] 10KB
    __shared__ __align__(16) float2 sU[256];
    __shared__ float s_b1[H], s_g[H], s_b[H], s_w2[H*4], s_b2[4], s_pw[8], s_pb[2];

    __nv_bfloat16* sAh = (__nv_bfloat16*)sPool;                // 64*40
    __nv_bfloat16* sAl = (__nv_bfloat16*)(sPool + 5120);       // 64*40

    const int tid = threadIdx.x, w = tid >> 5, lane = tid & 31;
    const int row0 = blockIdx.x * TM;

    #pragma unroll
    for (int it = 0; it < 2; it++)
        ((float4*)sU)[it*NTH + tid] = ((const float4*)g_U)[it*NTH + tid];
    if (tid < H){ s_b1[tid]=b1[tid]; s_g[tid]=lng[tid]; s_b[tid]=lnb[tid]; }
    #pragma unroll
    for (int it = 0; it < 2; it++) s_w2[it*NTH + tid] = w2[it*NTH + tid];
    if (tid < 4) s_b2[tid] = b2[tid];
    if (tid < 8) s_pw[tid] = pw[tid];
    if (tid < 2) s_pb[tid] = pb[tid];

    // ---- B staging: cp.async double buffer (5120B per chunk) ----
    auto stageB = [&](int ch, int buf){
        const char* srcB = (const char*)g_b + (size_t)ch*5120;
        char* dstB = (char*)&sB[buf][0];
        #pragma unroll
        for (int it = 0; it < 5; it++)
            cp16(dstB + (it*NTH + tid)*16, srcB + (it*NTH + tid)*16);
        asm volatile("cp.async.commit_group;");
    };

    // ---- x: direct coalesced LDG.128, register double buffer ----
    // lane -> row w*32 + it*4 + (lane>>3), 16B-seg lane&7. MLP = 8.
    float4 xp[8];
    const float* xbase = x + (size_t)(row0 + w*32 + (lane>>3))*DIN + (lane&7)*4;
    auto ldgX = [&](int ch){
        const float* p = xbase + ch*KC;
        const bool zpad = (ch == NCH-1) && ((lane&7) >= 4);   // k >= 784
        #pragma unroll
        for (int it = 0; it < 8; it++)
            xp[it] = zpad ? make_float4(0.f,0.f,0.f,0.f)
                          : *(const float4*)(p + (size_t)it*4*DIN);
    };

    wmma::fragment<wmma::accumulator, 16,16,16, float> acc[2][2];
    #pragma unroll
    for (int mt = 0; mt < 2; mt++)
        #pragma unroll
        for (int nt = 0; nt < 2; nt++) wmma::fill_fragment(acc[mt][nt], 0.f);

    stageB(0, 0);
    stageB(1, 1);
    ldgX(0);

    const uint acol = (lane & 7) * 4;             // bf16 col within A row
    const uint arow0 = w*32 + (lane >> 3);

    #pragma unroll 1
    for (int ch = 0; ch < NCH; ch++){
        const int buf = ch & 1;

        // --- convert regs -> bf16 hi/lo, STS.64 into A tiles ---
        #pragma unroll
        for (int it = 0; it < 8; it++){
            const float* f = (const float*)&xp[it];
            __nv_bfloat162 a0 = __float22bfloat162_rn(make_float2(f[0], f[1]));
            __nv_bfloat162 a1 = __float22bfloat162_rn(make_float2(f[2], f[3]));
            __nv_bfloat162 c0 = __float22bfloat162_rn(make_float2(
                f[0]-__bfloat162float(a0.x), f[1]-__bfloat162float(a0.y)));
            __nv_bfloat162 c1 = __float22bfloat162_rn(make_float2(
                f[2]-__bfloat162float(a1.x), f[3]-__bfloat162float(a1.y)));
            uint r = arow0 + it*4;
            *(uint2*)(sAh + r*LDA + acol) = make_uint2(*(uint*)&a0, *(uint*)&a1);
            *(uint2*)(sAl + r*LDA + acol) = make_uint2(*(uint*)&c0, *(uint*)&c1);
        }

        if (ch + 1 < NCH) ldgX(ch + 1);           // prefetch next chunk's x

        asm volatile("cp.async.wait_group 1;");   // B(ch) landed
        __syncthreads();                           // B + A tiles visible

        // --- 2 k-steps x (frag loads + 12 WMMA) ---
        const __nv_bfloat16* bBase = &sB[buf][0];
        #pragma unroll
        for (int ks = 0; ks < 2; ks++){
            wmma::fragment<wmma::matrix_a, 16,16,16, __nv_bfloat16, wmma::row_major> ah[2], al[2];
            wmma::fragment<wmma::matrix_b, 16,16,16, __nv_bfloat16, wmma::row_major> bh[2], bl[2];
            #pragma unroll
            for (int mt = 0; mt < 2; mt++){
                wmma::load_matrix_sync(ah[mt], sAh + (w*32 + mt*16)*LDA + ks*16, LDA);
                wmma::load_matrix_sync(al[mt], sAl + (w*32 + mt*16)*LDA + ks*16, LDA);
            }
            #pragma unroll
            for (int nt = 0; nt < 2; nt++){
                wmma::load_matrix_sync(bh[nt], bBase + ks*16*LDB + nt*16,          LDB);
                wmma::load_matrix_sync(bl[nt], bBase + KC*LDB + ks*16*LDB + nt*16, LDB);
            }
            #pragma unroll
            for (int mt = 0; mt < 2; mt++)
                #pragma unroll
                for (int nt = 0; nt < 2; nt++){
                    wmma::mma_sync(acc[mt][nt], ah[mt], bh[nt], acc[mt][nt]);
                    wmma::mma_sync(acc[mt][nt], ah[mt], bl[nt], acc[mt][nt]);
                    wmma::mma_sync(acc[mt][nt], al[mt], bh[nt], acc[mt][nt]);
                }
        }

        __syncthreads();                  // B buf + A tiles consumed
        if (ch + 2 < NCH) stageB(ch + 2, buf);
        else asm volatile("cp.async.commit_group;");   // keep FIFO accounting
    }

    asm volatile("cp.async.wait_group 0;");

    // --- h tile into sPool (overwrites A tiles; fenced by loop-end bar) ---
    float* sh = (float*)sPool;            // 64*36*4 = 9216 <= 10240
    #pragma unroll
    for (int mt = 0; mt < 2; mt++)
        #pragma unroll
        for (int nt = 0; nt < 2; nt++)
            wmma::store_matrix_sync(&sh[(w*32 + mt*16)*SHS + nt*16],
                                    acc[mt][nt], SHS, wmma::mem_row_major);
    __syncwarp();      // thread tid reads row tid: warp reads only its own rows

    {
        float h[32];
        const float4* hr = (const float4*)&sh[tid*SHS];
        #pragma unroll
        for (int q = 0; q < 8; q++){
            float4 v = hr[q];
            float v0 = v.x + s_b1[q*4],   v1 = v.y + s_b1[q*4+1];
            float v2 = v.z + s_b1[q*4+2], v3 = v.w + s_b1[q*4+3];
            h[q*4]   = v0 > 0.f ? v0 : 0.f;
            h[q*4+1] = v1 > 0.f ? v1 : 0.f;
            h[q*4+2] = v2 > 0.f ? v2 : 0.f;
            h[q*4+3] = v3 > 0.f ? v3 : 0.f;
        }
        float mu = 0.f;
        #pragma unroll
        for (int c = 0; c < 32; c++) mu += h[c];
        mu *= (1.f/32.f);
        float var = 0.f;
        #pragma unroll
        for (int c = 0; c < 32; c++){ float d = h[c]-mu; var += d*d; }
        var *= (1.f/32.f);
        float inv = rsqrtf(var + 1e-5f);

        float z0 = s_b2[0], z1 = s_b2[1], z2 = s_b2[2], z3 = s_b2[3];
        #pragma unroll
        for (int c = 0; c < 32; c++){
            float hn = (h[c]-mu)*inv*s_g[c] + s_b[c];
            z0 += hn * s_w2[c*4+0];
            z1 += hn * s_w2[c*4+1];
            z2 += hn * s_w2[c*4+2];
            z3 += hn * s_w2[c*4+3];
        }
        float cs[4], sn[4], zz;
        zz = tanhf(z0) * 1.5707963267948966f; sincosf(zz, &sn[0], &cs[0]);
        zz = tanhf(z1) * 1.5707963267948966f; sincosf(zz, &sn[1], &cs[1]);
        zz = tanhf(z2) * 1.5707963267948966f; sincosf(zz, &sn[2], &cs[2]);
        zz = tanhf(z3) * 1.5707963267948966f; sincosf(zz, &sn[3], &cs[3]);

        float t01[4], t23[4], psi[16];
        t01[0]=cs[0]*cs[1]; t01[1]=cs[0]*sn[1]; t01[2]=sn[0]*cs[1]; t01[3]=sn[0]*sn[1];
        t23[0]=cs[2]*cs[3]; t23[1]=cs[2]*sn[3]; t23[2]=sn[2]*cs[3]; t23[3]=sn[2]*sn[3];
        #pragma unroll
        for (int bb = 0; bb < 16; bb++) psi[bb] = t01[bb>>2]*t23[bb&3];

        float e0=0.f, e1=0.f, e2=0.f, e3=0.f;
        #pragma unroll 4
        for (int j = 0; j < 16; j++){
            float re = 0.f, im = 0.f;
            #pragma unroll
            for (int bb = 0; bb < 16; bb++){
                float2 u = sU[j*16 + bb];
                re += psi[bb]*u.x;
                im += psi[bb]*u.y;
            }
            float p = re*re + im*im;
            e0 += (j & 8) ? -p : p;
            e1 += (j & 4) ? -p : p;
            e2 += (j & 2) ? -p : p;
            e3 += (j & 1) ? -p : p;
        }
        float o0 = s_pb[0] + e0*s_pw[0] + e1*s_pw[2] + e2*s_pw[4] + e3*s_pw[6];
        float o1 = s_pb[1] + e0*s_pw[1] + e1*s_pw[3] + e2*s_pw[5] + e3*s_pw[7];
        out[row0 + tid] = make_float2(o0, o1);
    }
}

// ---------------------------------------------------------------------------
extern "C" void kernel_launch(void* const* d_in, const int* in_sizes, int n_in,
                              void* d_out, int out_size)
{
    const float* x   = (const float*)d_in[0];
    const float* w1  = (const float*)d_in[1];
    const float* b1  = (const float*)d_in[2];
    const float* lng = (const float*)d_in[3];
    const float* lnb = (const float*)d_in[4];
    const float* w2  = (const float*)d_in[5];
    const float* b2  = (const float*)d_in[6];
    const float* sw  = (const float*)d_in[7];
    const float* tw  = (const float*)d_in[8];
    const float* pw  = (const float*)d_in[9];
    const float* pb  = (const float*)d_in[10];
    (void)n_in; (void)out_size;

    int rows = in_sizes[0] / DIN;

    prologue_kernel<<<33, 128>>>(sw, tw, w1);
    fused_kernel<<<rows / TM, NTH>>>(x, b1, lng, lnb, w2, b2, pw, pb,
                                     (float2*)d_out);
}